// round 1
// baseline (speedup 1.0000x reference)
#include <cuda_runtime.h>
#include <math.h>

#define NMAX 100000
#define DIM  128
#define NG   128

// ---------------- scratch (device globals; no allocation allowed) -------------
__device__ float g_H[(size_t)NMAX * DIM];     // GEMM output per layer
__device__ float g_AGG[(size_t)NMAX * DIM];   // aggregated messages per layer
__device__ float g_dinv[NMAX];
__device__ int   g_deg[NMAX];
__device__ float g_sums[NG * DIM];
__device__ float g_cnt[NG];
__device__ float g_G1[NG * DIM];

// ---------------- degree / normalization -------------------------------------
__global__ void k_zero_deg(int n) {
    int i = blockIdx.x * blockDim.x + threadIdx.x;
    if (i < n) g_deg[i] = 0;
}
__global__ void k_deg(const int* __restrict__ dst, int E) {
    int e = blockIdx.x * blockDim.x + threadIdx.x;
    if (e < E) atomicAdd(&g_deg[dst[e]], 1);
}
__global__ void k_dinv(int n) {
    int i = blockIdx.x * blockDim.x + threadIdx.x;
    if (i < n) g_dinv[i] = rsqrtf((float)(g_deg[i] + 1));  // +1 for self-loop
}

// ---------------- GEMM: H = pre(X) @ W ---------------------------------------
// pre(X) = relu(X + bias) when useAgg (X = g_AGG); identity for raw input.
// M x 128 @ 128 x 128 fp32. BM=64, BN=128, BK=16, 256 threads.
#define BM 64
#define BN 128
#define BK 16
__global__ __launch_bounds__(256) void k_gemm(
    const float* __restrict__ Xext, const float* __restrict__ W,
    const float* __restrict__ bias, int useAgg, int M)
{
    __shared__ float As[BK][BM];
    __shared__ float Bs[BK][BN];
    const float* X = useAgg ? g_AGG : Xext;

    int tid  = threadIdx.x;
    int m0   = blockIdx.x * BM;
    int tcol = tid & 31;   // cols tcol*4 .. +4
    int trow = tid >> 5;   // rows trow*8 .. +8

    float acc[8][4];
#pragma unroll
    for (int r = 0; r < 8; r++)
#pragma unroll
        for (int c = 0; c < 4; c++) acc[r][c] = 0.f;

    int arow  = tid >> 2;        // 0..63
    int acol4 = (tid & 3) * 4;   // 0,4,8,12

    for (int kt = 0; kt < DIM; kt += BK) {
        // A tile: X[m0+arow][kt+acol4 ..+4]
        float4 av = make_float4(0.f, 0.f, 0.f, 0.f);
        int gm = m0 + arow;
        if (gm < M) av = *reinterpret_cast<const float4*>(X + (size_t)gm * DIM + kt + acol4);
        if (useAgg) {
            av.x = fmaxf(av.x + bias[kt + acol4 + 0], 0.f);
            av.y = fmaxf(av.y + bias[kt + acol4 + 1], 0.f);
            av.z = fmaxf(av.z + bias[kt + acol4 + 2], 0.f);
            av.w = fmaxf(av.w + bias[kt + acol4 + 3], 0.f);
        }
        As[acol4 + 0][arow] = av.x;
        As[acol4 + 1][arow] = av.y;
        As[acol4 + 2][arow] = av.z;
        As[acol4 + 3][arow] = av.w;
        // B tile: W[kt+bk][bn], 512 float4, 2 per thread
#pragma unroll
        for (int i = 0; i < 2; i++) {
            int idx = tid + i * 256;
            int bk  = idx >> 5;
            int bn  = (idx & 31) * 4;
            *reinterpret_cast<float4*>(&Bs[bk][bn]) =
                *reinterpret_cast<const float4*>(W + (size_t)(kt + bk) * DIM + bn);
        }
        __syncthreads();
#pragma unroll
        for (int kk = 0; kk < BK; kk++) {
            float4 b = *reinterpret_cast<const float4*>(&Bs[kk][tcol * 4]);
            float4 a0 = *reinterpret_cast<const float4*>(&As[kk][trow * 8]);
            float4 a1 = *reinterpret_cast<const float4*>(&As[kk][trow * 8 + 4]);
            float a[8] = {a0.x, a0.y, a0.z, a0.w, a1.x, a1.y, a1.z, a1.w};
#pragma unroll
            for (int r = 0; r < 8; r++) {
                acc[r][0] += a[r] * b.x;
                acc[r][1] += a[r] * b.y;
                acc[r][2] += a[r] * b.z;
                acc[r][3] += a[r] * b.w;
            }
        }
        __syncthreads();
    }
#pragma unroll
    for (int r = 0; r < 8; r++) {
        int gm = m0 + trow * 8 + r;
        if (gm < M) {
            float4 v = make_float4(acc[r][0], acc[r][1], acc[r][2], acc[r][3]);
            *reinterpret_cast<float4*>(&g_H[(size_t)gm * DIM + tcol * 4]) = v;
        }
    }
}

// ---------------- self-loop init: AGG[i] = H[i] * dinv[i]^2 -------------------
__global__ void k_selfloop(int n) {
    int t = blockIdx.x * blockDim.x + threadIdx.x;
    if (t >= n * 32) return;
    int node = t >> 5, q = (t & 31) * 4;
    float di = g_dinv[node];
    float s  = di * di;
    float4 h = *reinterpret_cast<const float4*>(&g_H[(size_t)node * DIM + q]);
    float4 v = make_float4(h.x * s, h.y * s, h.z * s, h.w * s);
    *reinterpret_cast<float4*>(&g_AGG[(size_t)node * DIM + q]) = v;
}

// ---------------- edge scatter: AGG[dst] += H[src] * norm ---------------------
__global__ void k_scatter(const int* __restrict__ src, const int* __restrict__ dst, int E) {
    int t = blockIdx.x * blockDim.x + threadIdx.x;
    int e = t >> 5;
    if (e >= E) return;
    int q = (t & 31) * 4;
    int s = src[e], d = dst[e];
    float nrm = g_dinv[s] * g_dinv[d];
    float4 h = *reinterpret_cast<const float4*>(&g_H[(size_t)s * DIM + q]);
    float* p = &g_AGG[(size_t)d * DIM + q];
    asm volatile("red.global.add.v4.f32 [%0], {%1, %2, %3, %4};"
                 :: "l"(p), "f"(h.x * nrm), "f"(h.y * nrm), "f"(h.z * nrm), "f"(h.w * nrm)
                 : "memory");
}

// ---------------- pooling ----------------------------------------------------
__global__ void k_zero_pool() {
    int i = blockIdx.x * blockDim.x + threadIdx.x;
    if (i < NG * DIM) g_sums[i] = 0.f;
    if (i < NG) g_cnt[i] = 0.f;
}
__global__ void k_pool(const int* __restrict__ batch, const float* __restrict__ bias, int n) {
    int t = blockIdx.x * blockDim.x + threadIdx.x;
    if (t >= n * 32) return;
    int node = t >> 5, lane = t & 31, q = lane * 4;
    int b = batch[node];
    float4 a = *reinterpret_cast<const float4*>(&g_AGG[(size_t)node * DIM + q]);
    float4 v;
    v.x = fmaxf(a.x + bias[q + 0], 0.f);
    v.y = fmaxf(a.y + bias[q + 1], 0.f);
    v.z = fmaxf(a.z + bias[q + 2], 0.f);
    v.w = fmaxf(a.w + bias[q + 3], 0.f);
    float* p = &g_sums[b * DIM + q];
    asm volatile("red.global.add.v4.f32 [%0], {%1, %2, %3, %4};"
                 :: "l"(p), "f"(v.x), "f"(v.y), "f"(v.z), "f"(v.w) : "memory");
    if (lane == 0) atomicAdd(&g_cnt[b], 1.0f);
}

// ---------------- head: lin1+relu, lin2, log_softmax --------------------------
__global__ void k_lin1(const float* __restrict__ w1, const float* __restrict__ b1) {
    int g = blockIdx.x;       // 128 graphs
    int j = threadIdx.x;      // 128 dims
    __shared__ float srow[DIM];
    float inv = 1.0f / fmaxf(g_cnt[g], 1.0f);
    srow[j] = g_sums[g * DIM + j] * inv;
    __syncthreads();
    float acc = b1[j];
#pragma unroll 8
    for (int k = 0; k < DIM; k++) acc += srow[k] * w1[k * DIM + j];
    g_G1[g * DIM + j] = fmaxf(acc, 0.f);
}
__global__ void k_head(const float* __restrict__ w2, const float* __restrict__ b2,
                       float* __restrict__ out) {
    int g = threadIdx.x;  // 128 graphs
    if (g >= NG) return;
    float l0 = b2[0], l1 = b2[1];
#pragma unroll 8
    for (int k = 0; k < DIM; k++) {
        float v = g_G1[g * DIM + k];
        l0 += v * w2[k * 2 + 0];
        l1 += v * w2[k * 2 + 1];
    }
    float m   = fmaxf(l0, l1);
    float lse = m + logf(expf(l0 - m) + expf(l1 - m));
    out[g * 2 + 0] = l0 - lse;
    out[g * 2 + 1] = l1 - lse;
}

// ---------------- launch ------------------------------------------------------
extern "C" void kernel_launch(void* const* d_in, const int* in_sizes, int n_in,
                              void* d_out, int out_size) {
    const float* x      = (const float*)d_in[0];
    const int*   ei     = (const int*)d_in[1];
    const int*   batch  = (const int*)d_in[2];
    const float* conv_w = (const float*)d_in[3];
    const float* conv_b = (const float*)d_in[4];
    const float* lin1_w = (const float*)d_in[5];
    const float* lin1_b = (const float*)d_in[6];
    const float* lin2_w = (const float*)d_in[7];
    const float* lin2_b = (const float*)d_in[8];
    float* out = (float*)d_out;

    int N = in_sizes[2];          // 100000 nodes
    int E = in_sizes[1] / 2;      // 1600000 edges
    const int* src = ei;
    const int* dst = ei + E;

    // degree + dinv
    k_zero_deg<<<(N + 255) / 256, 256>>>(N);
    k_deg<<<(E + 255) / 256, 256>>>(dst, E);
    k_dinv<<<(N + 255) / 256, 256>>>(N);

    int gemm_blocks = (N + BM - 1) / BM;
    int nodev_blocks = (N * 32 + 255) / 256;
    long scatter_threads = (long)E * 32;
    int scatter_blocks = (int)((scatter_threads + 255) / 256);

    for (int l = 0; l < 3; l++) {
        const float* bias = (l > 0) ? (conv_b + (size_t)(l - 1) * DIM) : conv_b;
        k_gemm<<<gemm_blocks, 256>>>(x, conv_w + (size_t)l * DIM * DIM, bias, l > 0 ? 1 : 0, N);
        k_selfloop<<<nodev_blocks, 256>>>(N);
        k_scatter<<<scatter_blocks, 256>>>(src, dst, E);
    }

    k_zero_pool<<<(NG * DIM + 255) / 256, 256>>>();
    k_pool<<<nodev_blocks, 256>>>(batch, conv_b + (size_t)2 * DIM, N);
    k_lin1<<<NG, DIM>>>(lin1_w, lin1_b);
    k_head<<<1, NG>>>(lin2_w, lin2_b, out);
}

// round 2
// speedup vs baseline: 2.0516x; 2.0516x over previous
#include <cuda_runtime.h>
#include <math.h>

#define NMAX 100000
#define EMAX 1600000
#define DIM  128
#define NG   128

// ---------------- scratch (device globals) ------------------------------------
__device__ float g_H[(size_t)NMAX * DIM];      // H' = (X@W) * dinv  per layer
__device__ float g_AGG[(size_t)NMAX * DIM];    // aggregated (pre-bias/relu)
__device__ float g_dinv[NMAX];
__device__ int   g_deg[NMAX];
__device__ int   g_fill[NMAX];
__device__ int   g_rowptr[NMAX + 1];
__device__ int   g_bsum[512];
__device__ int   g_csr[EMAX];                  // src index per edge, grouped by dst
__device__ float g_sums[NG * DIM];
__device__ float g_cnt[NG];
__device__ float g_G1[NG * DIM];

// ---------------- degree / normalization -------------------------------------
__global__ void k_zero_deg(int n) {
    int i = blockIdx.x * blockDim.x + threadIdx.x;
    if (i < n) { g_deg[i] = 0; g_fill[i] = 0; }
}
__global__ void k_deg(const int* __restrict__ dst, int E) {
    int e = blockIdx.x * blockDim.x + threadIdx.x;
    if (e < E) atomicAdd(&g_deg[dst[e]], 1);
}
__global__ void k_dinv(int n) {
    int i = blockIdx.x * blockDim.x + threadIdx.x;
    if (i < n) g_dinv[i] = rsqrtf((float)(g_deg[i] + 1));  // +1 self-loop
}

// ---------------- exclusive scan of deg -> rowptr (3 kernels) -----------------
__global__ __launch_bounds__(512) void k_scan1(int n) {
    __shared__ int wsum[16];
    int id = blockIdx.x * 512 + threadIdx.x;
    int lane = threadIdx.x & 31, w = threadIdx.x >> 5;
    int v = (id < n) ? g_deg[id] : 0;
    int incl = v;
#pragma unroll
    for (int o = 1; o < 32; o <<= 1) {
        int t = __shfl_up_sync(~0u, incl, o);
        if (lane >= o) incl += t;
    }
    if (lane == 31) wsum[w] = incl;
    __syncthreads();
    if (w == 0) {
        int s = (lane < 16) ? wsum[lane] : 0;
#pragma unroll
        for (int o = 1; o < 16; o <<= 1) {
            int t = __shfl_up_sync(~0u, s, o);
            if (lane >= o) s += t;
        }
        if (lane < 16) wsum[lane] = s;
    }
    __syncthreads();
    int woff = (w > 0) ? wsum[w - 1] : 0;
    if (id < n) g_rowptr[id] = woff + incl - v;          // exclusive, partial
    if (threadIdx.x == 511) g_bsum[blockIdx.x] = wsum[15]; // block total
}
__global__ __launch_bounds__(256) void k_scan2(int nb) {
    __shared__ int wsum[8];
    int tid = threadIdx.x, lane = tid & 31, w = tid >> 5;
    int v = (tid < nb) ? g_bsum[tid] : 0;
    int incl = v;
#pragma unroll
    for (int o = 1; o < 32; o <<= 1) {
        int t = __shfl_up_sync(~0u, incl, o);
        if (lane >= o) incl += t;
    }
    if (lane == 31) wsum[w] = incl;
    __syncthreads();
    if (w == 0) {
        int s = (lane < 8) ? wsum[lane] : 0;
#pragma unroll
        for (int o = 1; o < 8; o <<= 1) {
            int t = __shfl_up_sync(~0u, s, o);
            if (lane >= o) s += t;
        }
        if (lane < 8) wsum[lane] = s;
    }
    __syncthreads();
    int woff = (w > 0) ? wsum[w - 1] : 0;
    if (tid < nb) g_bsum[tid] = woff + incl - v;          // exclusive block offsets
}
__global__ __launch_bounds__(512) void k_scan3(int n, int E) {
    int id = blockIdx.x * 512 + threadIdx.x;
    if (id < n) g_rowptr[id] += g_bsum[blockIdx.x];
    if (id == 0) g_rowptr[n] = E;
}
__global__ void k_fill(const int* __restrict__ src, const int* __restrict__ dst, int E) {
    int e = blockIdx.x * blockDim.x + threadIdx.x;
    if (e < E) {
        int d = dst[e];
        int pos = g_rowptr[d] + atomicAdd(&g_fill[d], 1);
        g_csr[pos] = src[e];
    }
}

// ---------------- GEMM: H' = pre(X) @ W * dinv --------------------------------
#define BM 64
#define BN 128
#define BK 16
__global__ __launch_bounds__(256) void k_gemm(
    const float* __restrict__ Xext, const float* __restrict__ W,
    const float* __restrict__ bias, int useAgg, int M)
{
    __shared__ float As[BK][BM];
    __shared__ float Bs[BK][BN];
    const float* X = useAgg ? g_AGG : Xext;

    int tid  = threadIdx.x;
    int m0   = blockIdx.x * BM;
    int tcol = tid & 31;
    int trow = tid >> 5;

    float acc[8][4];
#pragma unroll
    for (int r = 0; r < 8; r++)
#pragma unroll
        for (int c = 0; c < 4; c++) acc[r][c] = 0.f;

    int arow  = tid >> 2;
    int acol4 = (tid & 3) * 4;

    for (int kt = 0; kt < DIM; kt += BK) {
        float4 av = make_float4(0.f, 0.f, 0.f, 0.f);
        int gm = m0 + arow;
        if (gm < M) av = *reinterpret_cast<const float4*>(X + (size_t)gm * DIM + kt + acol4);
        if (useAgg) {
            av.x = fmaxf(av.x + bias[kt + acol4 + 0], 0.f);
            av.y = fmaxf(av.y + bias[kt + acol4 + 1], 0.f);
            av.z = fmaxf(av.z + bias[kt + acol4 + 2], 0.f);
            av.w = fmaxf(av.w + bias[kt + acol4 + 3], 0.f);
        }
        As[acol4 + 0][arow] = av.x;
        As[acol4 + 1][arow] = av.y;
        As[acol4 + 2][arow] = av.z;
        As[acol4 + 3][arow] = av.w;
#pragma unroll
        for (int i = 0; i < 2; i++) {
            int idx = tid + i * 256;
            int bk  = idx >> 5;
            int bn  = (idx & 31) * 4;
            *reinterpret_cast<float4*>(&Bs[bk][bn]) =
                *reinterpret_cast<const float4*>(W + (size_t)(kt + bk) * DIM + bn);
        }
        __syncthreads();
#pragma unroll
        for (int kk = 0; kk < BK; kk++) {
            float4 b  = *reinterpret_cast<const float4*>(&Bs[kk][tcol * 4]);
            float4 a0 = *reinterpret_cast<const float4*>(&As[kk][trow * 8]);
            float4 a1 = *reinterpret_cast<const float4*>(&As[kk][trow * 8 + 4]);
            float a[8] = {a0.x, a0.y, a0.z, a0.w, a1.x, a1.y, a1.z, a1.w};
#pragma unroll
            for (int r = 0; r < 8; r++) {
                acc[r][0] += a[r] * b.x;
                acc[r][1] += a[r] * b.y;
                acc[r][2] += a[r] * b.z;
                acc[r][3] += a[r] * b.w;
            }
        }
        __syncthreads();
    }
#pragma unroll
    for (int r = 0; r < 8; r++) {
        int gm = m0 + trow * 8 + r;
        if (gm < M) {
            float di = g_dinv[gm];
            float4 v = make_float4(acc[r][0] * di, acc[r][1] * di,
                                   acc[r][2] * di, acc[r][3] * di);
            *reinterpret_cast<float4*>(&g_H[(size_t)gm * DIM + tcol * 4]) = v;
        }
    }
}

// ---------------- gather: AGG[d] = dinv[d] * (sum H'[src] + H'[d]) ------------
__global__ __launch_bounds__(256) void k_gather(int N) {
    int warp = (blockIdx.x * blockDim.x + threadIdx.x) >> 5;
    if (warp >= N) return;
    int q = (threadIdx.x & 31) * 4;

    int beg = g_rowptr[warp];
    int end = g_rowptr[warp + 1];

    // self-loop term
    float4 acc = *reinterpret_cast<const float4*>(&g_H[(size_t)warp * DIM + q]);

    int e = beg;
    for (; e + 4 <= end; e += 4) {
        int s0 = g_csr[e], s1 = g_csr[e + 1], s2 = g_csr[e + 2], s3 = g_csr[e + 3];
        float4 a = *reinterpret_cast<const float4*>(&g_H[(size_t)s0 * DIM + q]);
        float4 b = *reinterpret_cast<const float4*>(&g_H[(size_t)s1 * DIM + q]);
        float4 c = *reinterpret_cast<const float4*>(&g_H[(size_t)s2 * DIM + q]);
        float4 d = *reinterpret_cast<const float4*>(&g_H[(size_t)s3 * DIM + q]);
        acc.x += (a.x + b.x) + (c.x + d.x);
        acc.y += (a.y + b.y) + (c.y + d.y);
        acc.z += (a.z + b.z) + (c.z + d.z);
        acc.w += (a.w + b.w) + (c.w + d.w);
    }
    for (; e < end; e++) {
        int s = g_csr[e];
        float4 a = *reinterpret_cast<const float4*>(&g_H[(size_t)s * DIM + q]);
        acc.x += a.x; acc.y += a.y; acc.z += a.z; acc.w += a.w;
    }
    float di = g_dinv[warp];
    float4 v = make_float4(acc.x * di, acc.y * di, acc.z * di, acc.w * di);
    *reinterpret_cast<float4*>(&g_AGG[(size_t)warp * DIM + q]) = v;
}

// ---------------- pooling (run-length, batch is sorted) -----------------------
__global__ void k_zero_pool() {
    int i = blockIdx.x * blockDim.x + threadIdx.x;
    if (i < NG * DIM) g_sums[i] = 0.f;
    if (i < NG) g_cnt[i] = 0.f;
}
#define PCHUNK 32
__global__ __launch_bounds__(256) void k_pool(const int* __restrict__ batch,
                                              const float* __restrict__ bias, int n) {
    int warp = (blockIdx.x * blockDim.x + threadIdx.x) >> 5;
    int lane = threadIdx.x & 31;
    int q = lane * 4;
    int n0 = warp * PCHUNK;
    if (n0 >= n) return;
    int n1 = min(n0 + PCHUNK, n);

    float b0 = bias[q], b1 = bias[q + 1], b2 = bias[q + 2], b3 = bias[q + 3];

    float4 acc = make_float4(0.f, 0.f, 0.f, 0.f);
    float cnt = 0.f;
    int cur = batch[n0];
    for (int node = n0; node < n1; node++) {
        int bb = batch[node];
        if (bb != cur) {
            float* p = &g_sums[cur * DIM + q];
            asm volatile("red.global.add.v4.f32 [%0], {%1, %2, %3, %4};"
                         :: "l"(p), "f"(acc.x), "f"(acc.y), "f"(acc.z), "f"(acc.w) : "memory");
            if (lane == 0) atomicAdd(&g_cnt[cur], cnt);
            acc = make_float4(0.f, 0.f, 0.f, 0.f);
            cnt = 0.f;
            cur = bb;
        }
        float4 a = *reinterpret_cast<const float4*>(&g_AGG[(size_t)node * DIM + q]);
        acc.x += fmaxf(a.x + b0, 0.f);
        acc.y += fmaxf(a.y + b1, 0.f);
        acc.z += fmaxf(a.z + b2, 0.f);
        acc.w += fmaxf(a.w + b3, 0.f);
        cnt += 1.f;
    }
    float* p = &g_sums[cur * DIM + q];
    asm volatile("red.global.add.v4.f32 [%0], {%1, %2, %3, %4};"
                 :: "l"(p), "f"(acc.x), "f"(acc.y), "f"(acc.z), "f"(acc.w) : "memory");
    if (lane == 0) atomicAdd(&g_cnt[cur], cnt);
}

// ---------------- head --------------------------------------------------------
__global__ void k_lin1(const float* __restrict__ w1, const float* __restrict__ b1) {
    int g = blockIdx.x;
    int j = threadIdx.x;
    __shared__ float srow[DIM];
    float inv = 1.0f / fmaxf(g_cnt[g], 1.0f);
    srow[j] = g_sums[g * DIM + j] * inv;
    __syncthreads();
    float acc = b1[j];
#pragma unroll 8
    for (int k = 0; k < DIM; k++) acc += srow[k] * w1[k * DIM + j];
    g_G1[g * DIM + j] = fmaxf(acc, 0.f);
}
__global__ void k_head(const float* __restrict__ w2, const float* __restrict__ b2,
                       float* __restrict__ out) {
    int g = threadIdx.x;
    if (g >= NG) return;
    float l0 = b2[0], l1 = b2[1];
#pragma unroll 8
    for (int k = 0; k < DIM; k++) {
        float v = g_G1[g * DIM + k];
        l0 += v * w2[k * 2 + 0];
        l1 += v * w2[k * 2 + 1];
    }
    float m   = fmaxf(l0, l1);
    float lse = m + logf(expf(l0 - m) + expf(l1 - m));
    out[g * 2 + 0] = l0 - lse;
    out[g * 2 + 1] = l1 - lse;
}

// ---------------- launch ------------------------------------------------------
extern "C" void kernel_launch(void* const* d_in, const int* in_sizes, int n_in,
                              void* d_out, int out_size) {
    const float* x      = (const float*)d_in[0];
    const int*   ei     = (const int*)d_in[1];
    const int*   batch  = (const int*)d_in[2];
    const float* conv_w = (const float*)d_in[3];
    const float* conv_b = (const float*)d_in[4];
    const float* lin1_w = (const float*)d_in[5];
    const float* lin1_b = (const float*)d_in[6];
    const float* lin2_w = (const float*)d_in[7];
    const float* lin2_b = (const float*)d_in[8];
    float* out = (float*)d_out;

    int N = in_sizes[2];
    int E = in_sizes[1] / 2;
    const int* src = ei;
    const int* dst = ei + E;

    // degree + dinv + CSR build (once, reused by all 3 layers)
    k_zero_deg<<<(N + 255) / 256, 256>>>(N);
    k_deg<<<(E + 255) / 256, 256>>>(dst, E);
    k_dinv<<<(N + 255) / 256, 256>>>(N);

    int nb = (N + 511) / 512;
    k_scan1<<<nb, 512>>>(N);
    k_scan2<<<1, 256>>>(nb);
    k_scan3<<<nb, 512>>>(N, E);
    k_fill<<<(E + 255) / 256, 256>>>(src, dst, E);

    int gemm_blocks   = (N + BM - 1) / BM;
    int gather_blocks = (N * 32 + 255) / 256;

    for (int l = 0; l < 3; l++) {
        const float* bias = (l > 0) ? (conv_b + (size_t)(l - 1) * DIM) : conv_b;
        k_gemm<<<gemm_blocks, 256>>>(x, conv_w + (size_t)l * DIM * DIM, bias,
                                     l > 0 ? 1 : 0, N);
        k_gather<<<gather_blocks, 256>>>(N);
    }

    k_zero_pool<<<(NG * DIM + 255) / 256, 256>>>();
    int pool_warps = (N + PCHUNK - 1) / PCHUNK;
    k_pool<<<(pool_warps * 32 + 255) / 256, 256>>>(batch, conv_b + (size_t)2 * DIM, N);
    k_lin1<<<NG, DIM>>>(lin1_w, lin1_b);
    k_head<<<1, NG>>>(lin2_w, lin2_b, out);
}

// round 6
// speedup vs baseline: 2.4709x; 1.2044x over previous
#include <cuda_runtime.h>
#include <cuda_bf16.h>
#include <cstdint>
#include <math.h>

#define NMAX 100000
#define EMAX 1600000
#define DIM  128
#define NG   128

typedef unsigned int u32;

// ---------------- scratch (device globals) ------------------------------------
__device__ float g_H[(size_t)NMAX * DIM];      // H' = (X@W) * dinv  per layer
__device__ float g_AGG[(size_t)NMAX * DIM];    // aggregated (pre-bias/relu)
__device__ float g_dinv[NMAX];
__device__ int   g_deg[NMAX];
__device__ int   g_fill[NMAX];
__device__ int   g_rowptr[NMAX + 1];
__device__ int   g_bsum[512];
__device__ int   g_csr[EMAX];
__device__ float g_sums[NG * DIM];
__device__ float g_cnt[NG];
__device__ float g_G1[NG * DIM];

// ---------------- degree / normalization -------------------------------------
__global__ void k_zero_deg(int n) {
    int i = blockIdx.x * blockDim.x + threadIdx.x;
    if (i < n) { g_deg[i] = 0; g_fill[i] = 0; }
}
__global__ void k_deg(const int* __restrict__ dst, int E) {
    int e = blockIdx.x * blockDim.x + threadIdx.x;
    if (e < E) atomicAdd(&g_deg[dst[e]], 1);
}
__global__ void k_dinv(int n) {
    int i = blockIdx.x * blockDim.x + threadIdx.x;
    if (i < n) g_dinv[i] = rsqrtf((float)(g_deg[i] + 1));
}

// ---------------- exclusive scan of deg -> rowptr -----------------------------
__global__ __launch_bounds__(512) void k_scan1(int n) {
    __shared__ int wsum[16];
    int id = blockIdx.x * 512 + threadIdx.x;
    int lane = threadIdx.x & 31, w = threadIdx.x >> 5;
    int v = (id < n) ? g_deg[id] : 0;
    int incl = v;
#pragma unroll
    for (int o = 1; o < 32; o <<= 1) {
        int t = __shfl_up_sync(~0u, incl, o);
        if (lane >= o) incl += t;
    }
    if (lane == 31) wsum[w] = incl;
    __syncthreads();
    if (w == 0) {
        int s = (lane < 16) ? wsum[lane] : 0;
#pragma unroll
        for (int o = 1; o < 16; o <<= 1) {
            int t = __shfl_up_sync(~0u, s, o);
            if (lane >= o) s += t;
        }
        if (lane < 16) wsum[lane] = s;
    }
    __syncthreads();
    int woff = (w > 0) ? wsum[w - 1] : 0;
    if (id < n) g_rowptr[id] = woff + incl - v;
    if (threadIdx.x == 511) g_bsum[blockIdx.x] = wsum[15];
}
__global__ __launch_bounds__(256) void k_scan2(int nb) {
    __shared__ int wsum[8];
    int tid = threadIdx.x, lane = tid & 31, w = tid >> 5;
    int v = (tid < nb) ? g_bsum[tid] : 0;
    int incl = v;
#pragma unroll
    for (int o = 1; o < 32; o <<= 1) {
        int t = __shfl_up_sync(~0u, incl, o);
        if (lane >= o) incl += t;
    }
    if (lane == 31) wsum[w] = incl;
    __syncthreads();
    if (w == 0) {
        int s = (lane < 8) ? wsum[lane] : 0;
#pragma unroll
        for (int o = 1; o < 8; o <<= 1) {
            int t = __shfl_up_sync(~0u, s, o);
            if (lane >= o) s += t;
        }
        if (lane < 8) wsum[lane] = s;
    }
    __syncthreads();
    int woff = (w > 0) ? wsum[w - 1] : 0;
    if (tid < nb) g_bsum[tid] = woff + incl - v;
}
__global__ __launch_bounds__(512) void k_scan3(int n, int E) {
    int id = blockIdx.x * 512 + threadIdx.x;
    if (id < n) g_rowptr[id] += g_bsum[blockIdx.x];
    if (id == 0) g_rowptr[n] = E;
}
__global__ void k_fill(const int* __restrict__ src, const int* __restrict__ dst, int E) {
    int e = blockIdx.x * blockDim.x + threadIdx.x;
    if (e < E) {
        int d = dst[e];
        int pos = g_rowptr[d] + atomicAdd(&g_fill[d], 1);
        g_csr[pos] = src[e];
    }
}

// ---------------- tensor-core GEMM helpers ------------------------------------
#define ASTRIDE 40
#define BSTRIDE 136

__device__ __forceinline__ void bf16_split(float x, __nv_bfloat16& hi, __nv_bfloat16& lo) {
    hi = __float2bfloat16(x);
    lo = __float2bfloat16(x - __bfloat162float(hi));
}

__device__ __forceinline__ void ldsm4(u32 r[4], u32 addr) {
    asm volatile("ldmatrix.sync.aligned.m8n8.x4.shared.b16 {%0,%1,%2,%3}, [%4];"
                 : "=r"(r[0]), "=r"(r[1]), "=r"(r[2]), "=r"(r[3]) : "r"(addr));
}
__device__ __forceinline__ void ldsm4t(u32 r[4], u32 addr) {
    asm volatile("ldmatrix.sync.aligned.m8n8.x4.trans.shared.b16 {%0,%1,%2,%3}, [%4];"
                 : "=r"(r[0]), "=r"(r[1]), "=r"(r[2]), "=r"(r[3]) : "r"(addr));
}
__device__ __forceinline__ void mma16816(float c[4], const u32 a[4], u32 b0, u32 b1) {
    asm volatile("mma.sync.aligned.m16n8k16.row.col.f32.bf16.bf16.f32 "
                 "{%0,%1,%2,%3}, {%4,%5,%6,%7}, {%8,%9}, {%0,%1,%2,%3};"
                 : "+f"(c[0]), "+f"(c[1]), "+f"(c[2]), "+f"(c[3])
                 : "r"(a[0]), "r"(a[1]), "r"(a[2]), "r"(a[3]), "r"(b0), "r"(b1));
}

// H' = relu(pre(X)) @ W * dinv ; bf16 2-way split (Xhi@Whi + Xhi@Wlo + Xlo@Whi)
// Block: 128 rows x 128 cols, K chunks of 32, 256 threads (8 warps x 16 rows).
__global__ __launch_bounds__(256, 2) void k_gemm_mma(
    const float* __restrict__ Xext, const float* __restrict__ W,
    const float* __restrict__ bias, int useAgg, int M)
{
    __shared__ alignas(16) __nv_bfloat16 sAhi[128 * ASTRIDE];
    __shared__ alignas(16) __nv_bfloat16 sAlo[128 * ASTRIDE];
    __shared__ alignas(16) __nv_bfloat16 sBhi[32 * BSTRIDE];
    __shared__ alignas(16) __nv_bfloat16 sBlo[32 * BSTRIDE];

    const float* X = useAgg ? g_AGG : Xext;
    int tid  = threadIdx.x;
    int lane = tid & 31, warp = tid >> 5;
    int m0   = blockIdx.x * 128;
    int grp  = lane >> 2, tig = lane & 3;

    // ldmatrix per-thread source row/col (within a 16x16 bf16 tile)
    int sub  = lane >> 3;                      // 0..3
    int lrow = (lane & 7) + ((sub & 1) << 3);  // 0..15
    int lcol = (sub >> 1) << 3;                // 0 or 8

    float acc[16][4];
#pragma unroll
    for (int nt = 0; nt < 16; nt++)
#pragma unroll
        for (int c = 0; c < 4; c++) acc[nt][c] = 0.f;

    for (int kc = 0; kc < 4; kc++) {
        // ---- load + split A chunk [128 x 32] ----
#pragma unroll
        for (int i = 0; i < 4; i++) {
            int f   = tid + (i << 8);      // float4 id 0..1023
            int row = f >> 3;              // 0..127
            int c   = (f & 7) << 2;        // 0..28
            int gr  = m0 + row;
            float4 v = make_float4(0.f, 0.f, 0.f, 0.f);
            if (gr < M)
                v = *reinterpret_cast<const float4*>(X + (size_t)gr * DIM + kc * 32 + c);
            if (useAgg) {
                v.x = fmaxf(v.x + bias[kc * 32 + c + 0], 0.f);
                v.y = fmaxf(v.y + bias[kc * 32 + c + 1], 0.f);
                v.z = fmaxf(v.z + bias[kc * 32 + c + 2], 0.f);
                v.w = fmaxf(v.w + bias[kc * 32 + c + 3], 0.f);
            }
            int base = row * ASTRIDE + c;
            bf16_split(v.x, sAhi[base + 0], sAlo[base + 0]);
            bf16_split(v.y, sAhi[base + 1], sAlo[base + 1]);
            bf16_split(v.z, sAhi[base + 2], sAlo[base + 2]);
            bf16_split(v.w, sAhi[base + 3], sAlo[base + 3]);
        }
        // ---- load + split B chunk W[32 x 128] ----
#pragma unroll
        for (int i = 0; i < 4; i++) {
            int f   = tid + (i << 8);
            int row = f >> 5;              // 0..31
            int c   = (f & 31) << 2;       // 0..124
            float4 v = *reinterpret_cast<const float4*>(W + (size_t)(kc * 32 + row) * DIM + c);
            int base = row * BSTRIDE + c;
            bf16_split(v.x, sBhi[base + 0], sBlo[base + 0]);
            bf16_split(v.y, sBhi[base + 1], sBlo[base + 1]);
            bf16_split(v.z, sBhi[base + 2], sBlo[base + 2]);
            bf16_split(v.w, sBhi[base + 3], sBlo[base + 3]);
        }
        __syncthreads();

#pragma unroll
        for (int ks = 0; ks < 2; ks++) {
            u32 fragAh[4], fragAl[4];
            u32 aHiAddr = (u32)__cvta_generic_to_shared(
                &sAhi[(16 * warp + lrow) * ASTRIDE + 16 * ks + lcol]);
            u32 aLoAddr = (u32)__cvta_generic_to_shared(
                &sAlo[(16 * warp + lrow) * ASTRIDE + 16 * ks + lcol]);
            ldsm4(fragAh, aHiAddr);
            ldsm4(fragAl, aLoAddr);
#pragma unroll
            for (int n0 = 0; n0 < 8; n0++) {
                u32 fragBh[4], fragBl[4];
                u32 bHiAddr = (u32)__cvta_generic_to_shared(
                    &sBhi[(16 * ks + lrow) * BSTRIDE + 16 * n0 + lcol]);
                u32 bLoAddr = (u32)__cvta_generic_to_shared(
                    &sBlo[(16 * ks + lrow) * BSTRIDE + 16 * n0 + lcol]);
                ldsm4t(fragBh, bHiAddr);
                ldsm4t(fragBl, bLoAddr);
                mma16816(acc[2 * n0],     fragAh, fragBh[0], fragBh[1]);
                mma16816(acc[2 * n0],     fragAh, fragBl[0], fragBl[1]);
                mma16816(acc[2 * n0],     fragAl, fragBh[0], fragBh[1]);
                mma16816(acc[2 * n0 + 1], fragAh, fragBh[2], fragBh[3]);
                mma16816(acc[2 * n0 + 1], fragAh, fragBl[2], fragBl[3]);
                mma16816(acc[2 * n0 + 1], fragAl, fragBh[2], fragBh[3]);
            }
        }
        __syncthreads();
    }

    // ---- epilogue: scale by dinv, store ----
    int r0 = m0 + 16 * warp + grp;
    int r1 = r0 + 8;
    float d0 = (r0 < M) ? g_dinv[r0] : 0.f;
    float d1 = (r1 < M) ? g_dinv[r1] : 0.f;
#pragma unroll
    for (int nt = 0; nt < 16; nt++) {
        int col = 8 * nt + 2 * tig;
        if (r0 < M) {
            float2 v = make_float2(acc[nt][0] * d0, acc[nt][1] * d0);
            *reinterpret_cast<float2*>(&g_H[(size_t)r0 * DIM + col]) = v;
        }
        if (r1 < M) {
            float2 v = make_float2(acc[nt][2] * d1, acc[nt][3] * d1);
            *reinterpret_cast<float2*>(&g_H[(size_t)r1 * DIM + col]) = v;
        }
    }
}

// ---------------- gather: AGG[d] = dinv[d] * (sum H'[src] + H'[d]) ------------
__global__ __launch_bounds__(256) void k_gather(int N) {
    int warp = (blockIdx.x * blockDim.x + threadIdx.x) >> 5;
    if (warp >= N) return;
    int q = (threadIdx.x & 31) * 4;

    int beg = g_rowptr[warp];
    int end = g_rowptr[warp + 1];

    float4 acc = *reinterpret_cast<const float4*>(&g_H[(size_t)warp * DIM + q]);

    int e = beg;
    for (; e + 4 <= end; e += 4) {
        int s0 = g_csr[e], s1 = g_csr[e + 1], s2 = g_csr[e + 2], s3 = g_csr[e + 3];
        float4 a = *reinterpret_cast<const float4*>(&g_H[(size_t)s0 * DIM + q]);
        float4 b = *reinterpret_cast<const float4*>(&g_H[(size_t)s1 * DIM + q]);
        float4 c = *reinterpret_cast<const float4*>(&g_H[(size_t)s2 * DIM + q]);
        float4 d = *reinterpret_cast<const float4*>(&g_H[(size_t)s3 * DIM + q]);
        acc.x += (a.x + b.x) + (c.x + d.x);
        acc.y += (a.y + b.y) + (c.y + d.y);
        acc.z += (a.z + b.z) + (c.z + d.z);
        acc.w += (a.w + b.w) + (c.w + d.w);
    }
    for (; e < end; e++) {
        int s = g_csr[e];
        float4 a = *reinterpret_cast<const float4*>(&g_H[(size_t)s * DIM + q]);
        acc.x += a.x; acc.y += a.y; acc.z += a.z; acc.w += a.w;
    }
    float di = g_dinv[warp];
    float4 v = make_float4(acc.x * di, acc.y * di, acc.z * di, acc.w * di);
    *reinterpret_cast<float4*>(&g_AGG[(size_t)warp * DIM + q]) = v;
}

// ---------------- pooling (run-length, batch sorted) --------------------------
__global__ void k_zero_pool() {
    int i = blockIdx.x * blockDim.x + threadIdx.x;
    if (i < NG * DIM) g_sums[i] = 0.f;
    if (i < NG) g_cnt[i] = 0.f;
}
#define PCHUNK 32
__global__ __launch_bounds__(256) void k_pool(const int* __restrict__ batch,
                                              const float* __restrict__ bias, int n) {
    int warp = (blockIdx.x * blockDim.x + threadIdx.x) >> 5;
    int lane = threadIdx.x & 31;
    int q = lane * 4;
    int n0 = warp * PCHUNK;
    if (n0 >= n) return;
    int n1 = min(n0 + PCHUNK, n);

    float b0 = bias[q], b1 = bias[q + 1], b2 = bias[q + 2], b3 = bias[q + 3];

    float4 acc = make_float4(0.f, 0.f, 0.f, 0.f);
    float cnt = 0.f;
    int cur = batch[n0];
    for (int node = n0; node < n1; node++) {
        int bb = batch[node];
        if (bb != cur) {
            float* p = &g_sums[cur * DIM + q];
            asm volatile("red.global.add.v4.f32 [%0], {%1, %2, %3, %4};"
                         :: "l"(p), "f"(acc.x), "f"(acc.y), "f"(acc.z), "f"(acc.w) : "memory");
            if (lane == 0) atomicAdd(&g_cnt[cur], cnt);
            acc = make_float4(0.f, 0.f, 0.f, 0.f);
            cnt = 0.f;
            cur = bb;
        }
        float4 a = *reinterpret_cast<const float4*>(&g_AGG[(size_t)node * DIM + q]);
        acc.x += fmaxf(a.x + b0, 0.f);
        acc.y += fmaxf(a.y + b1, 0.f);
        acc.z += fmaxf(a.z + b2, 0.f);
        acc.w += fmaxf(a.w + b3, 0.f);
        cnt += 1.f;
    }
    float* p = &g_sums[cur * DIM + q];
    asm volatile("red.global.add.v4.f32 [%0], {%1, %2, %3, %4};"
                 :: "l"(p), "f"(acc.x), "f"(acc.y), "f"(acc.z), "f"(acc.w) : "memory");
    if (lane == 0) atomicAdd(&g_cnt[cur], cnt);
}

// ---------------- head --------------------------------------------------------
__global__ void k_lin1(const float* __restrict__ w1, const float* __restrict__ b1) {
    int g = blockIdx.x;
    int j = threadIdx.x;
    __shared__ float srow[DIM];
    float inv = 1.0f / fmaxf(g_cnt[g], 1.0f);
    srow[j] = g_sums[g * DIM + j] * inv;
    __syncthreads();
    float acc = b1[j];
#pragma unroll 8
    for (int k = 0; k < DIM; k++) acc += srow[k] * w1[k * DIM + j];
    g_G1[g * DIM + j] = fmaxf(acc, 0.f);
}
__global__ void k_head(const float* __restrict__ w2, const float* __restrict__ b2,
                       float* __restrict__ out) {
    int g = threadIdx.x;
    if (g >= NG) return;
    float l0 = b2[0], l1 = b2[1];
#pragma unroll 8
    for (int k = 0; k < DIM; k++) {
        float v = g_G1[g * DIM + k];
        l0 += v * w2[k * 2 + 0];
        l1 += v * w2[k * 2 + 1];
    }
    float m   = fmaxf(l0, l1);
    float lse = m + logf(expf(l0 - m) + expf(l1 - m));
    out[g * 2 + 0] = l0 - lse;
    out[g * 2 + 1] = l1 - lse;
}

// ---------------- launch ------------------------------------------------------
extern "C" void kernel_launch(void* const* d_in, const int* in_sizes, int n_in,
                              void* d_out, int out_size) {
    const float* x      = (const float*)d_in[0];
    const int*   ei     = (const int*)d_in[1];
    const int*   batch  = (const int*)d_in[2];
    const float* conv_w = (const float*)d_in[3];
    const float* conv_b = (const float*)d_in[4];
    const float* lin1_w = (const float*)d_in[5];
    const float* lin1_b = (const float*)d_in[6];
    const float* lin2_w = (const float*)d_in[7];
    const float* lin2_b = (const float*)d_in[8];
    float* out = (float*)d_out;

    int N = in_sizes[2];
    int E = in_sizes[1] / 2;
    const int* src = ei;
    const int* dst = ei + E;

    k_zero_deg<<<(N + 255) / 256, 256>>>(N);
    k_deg<<<(E + 255) / 256, 256>>>(dst, E);
    k_dinv<<<(N + 255) / 256, 256>>>(N);

    int nb = (N + 511) / 512;
    k_scan1<<<nb, 512>>>(N);
    k_scan2<<<1, 256>>>(nb);
    k_scan3<<<nb, 512>>>(N, E);
    k_fill<<<(E + 255) / 256, 256>>>(src, dst, E);

    int gemm_blocks   = (N + 127) / 128;
    int gather_blocks = (N * 32 + 255) / 256;

    for (int l = 0; l < 3; l++) {
        const float* bias = (l > 0) ? (conv_b + (size_t)(l - 1) * DIM) : conv_b;
        k_gemm_mma<<<gemm_blocks, 256>>>(x, conv_w + (size_t)l * DIM * DIM, bias,
                                         l > 0 ? 1 : 0, N);
        k_gather<<<gather_blocks, 256>>>(N);
    }

    k_zero_pool<<<(NG * DIM + 255) / 256, 256>>>();
    int pool_warps = (N + PCHUNK - 1) / PCHUNK;
    k_pool<<<(pool_warps * 32 + 255) / 256, 256>>>(batch, conv_b + (size_t)2 * DIM, N);
    k_lin1<<<NG, DIM>>>(lin1_w, lin1_b);
    k_head<<<1, NG>>>(lin2_w, lin2_b, out);
}

// round 8
// speedup vs baseline: 3.1501x; 1.2749x over previous
#include <cuda_runtime.h>
#include <cuda_bf16.h>
#include <cuda_fp16.h>
#include <cstdint>
#include <math.h>

#define NMAX 100000
#define EMAX 1600000
#define DIM  128
#define NG   128

typedef unsigned int u32;

// ---------------- scratch (device globals) ------------------------------------
__device__ __half g_H16[(size_t)NMAX * DIM];    // H' = (X@W) * dinv  (fp16)
__device__ __half g_AGG16[(size_t)NMAX * DIM];  // aggregated pre-bias/relu (fp16)
__device__ float g_dinv[NMAX];
__device__ int   g_deg[NMAX];
__device__ int   g_fill[NMAX];
__device__ int   g_rowptr[NMAX + 1];
__device__ int   g_bsum[512];
__device__ int   g_csr[EMAX];
__device__ float g_sums[NG * DIM];
__device__ float g_cnt[NG];
__device__ float g_G1[NG * DIM];

// ---------------- degree / normalization -------------------------------------
__global__ void k_zero_deg(int n) {
    int i = blockIdx.x * blockDim.x + threadIdx.x;
    if (i < n) { g_deg[i] = 0; g_fill[i] = 0; }
}
__global__ void k_deg(const int* __restrict__ dst, int E) {
    int e = blockIdx.x * blockDim.x + threadIdx.x;
    if (e < E) atomicAdd(&g_deg[dst[e]], 1);
}
__global__ void k_dinv(int n) {
    int i = blockIdx.x * blockDim.x + threadIdx.x;
    if (i < n) g_dinv[i] = rsqrtf((float)(g_deg[i] + 1));
}

// ---------------- exclusive scan of deg -> rowptr -----------------------------
__global__ __launch_bounds__(512) void k_scan1(int n) {
    __shared__ int wsum[16];
    int id = blockIdx.x * 512 + threadIdx.x;
    int lane = threadIdx.x & 31, w = threadIdx.x >> 5;
    int v = (id < n) ? g_deg[id] : 0;
    int incl = v;
#pragma unroll
    for (int o = 1; o < 32; o <<= 1) {
        int t = __shfl_up_sync(~0u, incl, o);
        if (lane >= o) incl += t;
    }
    if (lane == 31) wsum[w] = incl;
    __syncthreads();
    if (w == 0) {
        int s = (lane < 16) ? wsum[lane] : 0;
#pragma unroll
        for (int o = 1; o < 16; o <<= 1) {
            int t = __shfl_up_sync(~0u, s, o);
            if (lane >= o) s += t;
        }
        if (lane < 16) wsum[lane] = s;
    }
    __syncthreads();
    int woff = (w > 0) ? wsum[w - 1] : 0;
    if (id < n) g_rowptr[id] = woff + incl - v;
    if (threadIdx.x == 511) g_bsum[blockIdx.x] = wsum[15];
}
__global__ __launch_bounds__(256) void k_scan2(int nb) {
    __shared__ int wsum[8];
    int tid = threadIdx.x, lane = tid & 31, w = tid >> 5;
    int v = (tid < nb) ? g_bsum[tid] : 0;
    int incl = v;
#pragma unroll
    for (int o = 1; o < 32; o <<= 1) {
        int t = __shfl_up_sync(~0u, incl, o);
        if (lane >= o) incl += t;
    }
    if (lane == 31) wsum[w] = incl;
    __syncthreads();
    if (w == 0) {
        int s = (lane < 8) ? wsum[lane] : 0;
#pragma unroll
        for (int o = 1; o < 8; o <<= 1) {
            int t = __shfl_up_sync(~0u, s, o);
            if (lane >= o) s += t;
        }
        if (lane < 8) wsum[lane] = s;
    }
    __syncthreads();
    int woff = (w > 0) ? wsum[w - 1] : 0;
    if (tid < nb) g_bsum[tid] = woff + incl - v;
}
__global__ __launch_bounds__(512) void k_scan3(int n, int E) {
    int id = blockIdx.x * 512 + threadIdx.x;
    if (id < n) g_rowptr[id] += g_bsum[blockIdx.x];
    if (id == 0) g_rowptr[n] = E;
}
__global__ void k_fill(const int* __restrict__ src, const int* __restrict__ dst, int E) {
    int e = blockIdx.x * blockDim.x + threadIdx.x;
    if (e < E) {
        int d = dst[e];
        int pos = g_rowptr[d] + atomicAdd(&g_fill[d], 1);
        g_csr[pos] = src[e];
    }
}

// ---------------- tensor-core GEMM helpers ------------------------------------
#define ASTRIDE 40
#define BSTRIDE 136

__device__ __forceinline__ void bf16_split(float x, __nv_bfloat16& hi, __nv_bfloat16& lo) {
    hi = __float2bfloat16(x);
    lo = __float2bfloat16(x - __bfloat162float(hi));
}

__device__ __forceinline__ void ldsm4(u32 r[4], u32 addr) {
    asm volatile("ldmatrix.sync.aligned.m8n8.x4.shared.b16 {%0,%1,%2,%3}, [%4];"
                 : "=r"(r[0]), "=r"(r[1]), "=r"(r[2]), "=r"(r[3]) : "r"(addr));
}
__device__ __forceinline__ void ldsm4t(u32 r[4], u32 addr) {
    asm volatile("ldmatrix.sync.aligned.m8n8.x4.trans.shared.b16 {%0,%1,%2,%3}, [%4];"
                 : "=r"(r[0]), "=r"(r[1]), "=r"(r[2]), "=r"(r[3]) : "r"(addr));
}
__device__ __forceinline__ void mma16816(float c[4], const u32 a[4], u32 b0, u32 b1) {
    asm volatile("mma.sync.aligned.m16n8k16.row.col.f32.bf16.bf16.f32 "
                 "{%0,%1,%2,%3}, {%4,%5,%6,%7}, {%8,%9}, {%0,%1,%2,%3};"
                 : "+f"(c[0]), "+f"(c[1]), "+f"(c[2]), "+f"(c[3])
                 : "r"(a[0]), "r"(a[1]), "r"(a[2]), "r"(a[3]), "r"(b0), "r"(b1));
}

// H' = relu(pre(X)) @ W * dinv ; bf16 2-way split (Xhi@Whi + Xhi@Wlo + Xlo@Whi)
// Layer 0 reads fp32 x; layers 1+ read fp16 AGG (+bias, relu). Output fp16 H'.
__global__ __launch_bounds__(256, 2) void k_gemm_mma(
    const float* __restrict__ Xext, const float* __restrict__ W,
    const float* __restrict__ bias, int useAgg, int M)
{
    __shared__ alignas(16) __nv_bfloat16 sAhi[128 * ASTRIDE];
    __shared__ alignas(16) __nv_bfloat16 sAlo[128 * ASTRIDE];
    __shared__ alignas(16) __nv_bfloat16 sBhi[32 * BSTRIDE];
    __shared__ alignas(16) __nv_bfloat16 sBlo[32 * BSTRIDE];

    int tid  = threadIdx.x;
    int lane = tid & 31, warp = tid >> 5;
    int m0   = blockIdx.x * 128;
    int grp  = lane >> 2, tig = lane & 3;

    int sub  = lane >> 3;
    int lrow = (lane & 7) + ((sub & 1) << 3);
    int lcol = (sub >> 1) << 3;

    float acc[16][4];
#pragma unroll
    for (int nt = 0; nt < 16; nt++)
#pragma unroll
        for (int c = 0; c < 4; c++) acc[nt][c] = 0.f;

    for (int kc = 0; kc < 4; kc++) {
        // ---- load + split A chunk [128 x 32] ----
#pragma unroll
        for (int i = 0; i < 4; i++) {
            int f   = tid + (i << 8);
            int row = f >> 3;
            int c   = (f & 7) << 2;
            int gr  = m0 + row;
            float4 v = make_float4(0.f, 0.f, 0.f, 0.f);
            if (useAgg) {
                if (gr < M) {
                    uint2 raw = *reinterpret_cast<const uint2*>(
                        &g_AGG16[(size_t)gr * DIM + kc * 32 + c]);
                    float2 f0 = __half22float2(*reinterpret_cast<__half2*>(&raw.x));
                    float2 f1 = __half22float2(*reinterpret_cast<__half2*>(&raw.y));
                    v = make_float4(f0.x, f0.y, f1.x, f1.y);
                }
                v.x = fmaxf(v.x + bias[kc * 32 + c + 0], 0.f);
                v.y = fmaxf(v.y + bias[kc * 32 + c + 1], 0.f);
                v.z = fmaxf(v.z + bias[kc * 32 + c + 2], 0.f);
                v.w = fmaxf(v.w + bias[kc * 32 + c + 3], 0.f);
            } else {
                if (gr < M)
                    v = *reinterpret_cast<const float4*>(Xext + (size_t)gr * DIM + kc * 32 + c);
            }
            int base = row * ASTRIDE + c;
            bf16_split(v.x, sAhi[base + 0], sAlo[base + 0]);
            bf16_split(v.y, sAhi[base + 1], sAlo[base + 1]);
            bf16_split(v.z, sAhi[base + 2], sAlo[base + 2]);
            bf16_split(v.w, sAhi[base + 3], sAlo[base + 3]);
        }
        // ---- load + split B chunk W[32 x 128] ----
#pragma unroll
        for (int i = 0; i < 4; i++) {
            int f   = tid + (i << 8);
            int row = f >> 5;
            int c   = (f & 31) << 2;
            float4 v = *reinterpret_cast<const float4*>(W + (size_t)(kc * 32 + row) * DIM + c);
            int base = row * BSTRIDE + c;
            bf16_split(v.x, sBhi[base + 0], sBlo[base + 0]);
            bf16_split(v.y, sBhi[base + 1], sBlo[base + 1]);
            bf16_split(v.z, sBhi[base + 2], sBlo[base + 2]);
            bf16_split(v.w, sBhi[base + 3], sBlo[base + 3]);
        }
        __syncthreads();

#pragma unroll
        for (int ks = 0; ks < 2; ks++) {
            u32 fragAh[4], fragAl[4];
            u32 aHiAddr = (u32)__cvta_generic_to_shared(
                &sAhi[(16 * warp + lrow) * ASTRIDE + 16 * ks + lcol]);
            u32 aLoAddr = (u32)__cvta_generic_to_shared(
                &sAlo[(16 * warp + lrow) * ASTRIDE + 16 * ks + lcol]);
            ldsm4(fragAh, aHiAddr);
            ldsm4(fragAl, aLoAddr);
#pragma unroll
            for (int n0 = 0; n0 < 8; n0++) {
                u32 fragBh[4], fragBl[4];
                u32 bHiAddr = (u32)__cvta_generic_to_shared(
                    &sBhi[(16 * ks + lrow) * BSTRIDE + 16 * n0 + lcol]);
                u32 bLoAddr = (u32)__cvta_generic_to_shared(
                    &sBlo[(16 * ks + lrow) * BSTRIDE + 16 * n0 + lcol]);
                ldsm4t(fragBh, bHiAddr);
                ldsm4t(fragBl, bLoAddr);
                mma16816(acc[2 * n0],     fragAh, fragBh[0], fragBh[1]);
                mma16816(acc[2 * n0],     fragAh, fragBl[0], fragBl[1]);
                mma16816(acc[2 * n0],     fragAl, fragBh[0], fragBh[1]);
                mma16816(acc[2 * n0 + 1], fragAh, fragBh[2], fragBh[3]);
                mma16816(acc[2 * n0 + 1], fragAh, fragBl[2], fragBl[3]);
                mma16816(acc[2 * n0 + 1], fragAl, fragBh[2], fragBh[3]);
            }
        }
        __syncthreads();
    }

    // ---- epilogue: scale by dinv, store fp16 ----
    int r0 = m0 + 16 * warp + grp;
    int r1 = r0 + 8;
    float d0 = (r0 < M) ? g_dinv[r0] : 0.f;
    float d1 = (r1 < M) ? g_dinv[r1] : 0.f;
#pragma unroll
    for (int nt = 0; nt < 16; nt++) {
        int col = 8 * nt + 2 * tig;
        if (r0 < M) {
            __half2 h = __floats2half2_rn(acc[nt][0] * d0, acc[nt][1] * d0);
            *reinterpret_cast<__half2*>(&g_H16[(size_t)r0 * DIM + col]) = h;
        }
        if (r1 < M) {
            __half2 h = __floats2half2_rn(acc[nt][2] * d1, acc[nt][3] * d1);
            *reinterpret_cast<__half2*>(&g_H16[(size_t)r1 * DIM + col]) = h;
        }
    }
}

// ---------------- gather: AGG[d] = dinv[d] * (sum H'[src] + H'[d]) ------------
// fp16 rows (8 bytes per lane), fp32 accumulation.
__device__ __forceinline__ void acc_row(float4& acc, uint2 raw) {
    float2 f0 = __half22float2(*reinterpret_cast<__half2*>(&raw.x));
    float2 f1 = __half22float2(*reinterpret_cast<__half2*>(&raw.y));
    acc.x += f0.x; acc.y += f0.y; acc.z += f1.x; acc.w += f1.y;
}
__global__ __launch_bounds__(256) void k_gather(int N) {
    int warp = (blockIdx.x * blockDim.x + threadIdx.x) >> 5;
    if (warp >= N) return;
    int lane = threadIdx.x & 31;

    const uint2* Hv = reinterpret_cast<const uint2*>(g_H16);  // 32 uint2 per row
    int beg = g_rowptr[warp];
    int end = g_rowptr[warp + 1];

    float4 acc = make_float4(0.f, 0.f, 0.f, 0.f);
    acc_row(acc, Hv[(size_t)warp * 32 + lane]);   // self-loop

    int e = beg;
    for (; e + 4 <= end; e += 4) {
        int s0 = g_csr[e], s1 = g_csr[e + 1], s2 = g_csr[e + 2], s3 = g_csr[e + 3];
        uint2 r0 = Hv[(size_t)s0 * 32 + lane];
        uint2 r1 = Hv[(size_t)s1 * 32 + lane];
        uint2 r2 = Hv[(size_t)s2 * 32 + lane];
        uint2 r3 = Hv[(size_t)s3 * 32 + lane];
        acc_row(acc, r0); acc_row(acc, r1); acc_row(acc, r2); acc_row(acc, r3);
    }
    for (; e < end; e++)
        acc_row(acc, Hv[(size_t)g_csr[e] * 32 + lane]);

    float di = g_dinv[warp];
    __half2 h0 = __floats2half2_rn(acc.x * di, acc.y * di);
    __half2 h1 = __floats2half2_rn(acc.z * di, acc.w * di);
    uint2 outv;
    outv.x = *reinterpret_cast<u32*>(&h0);
    outv.y = *reinterpret_cast<u32*>(&h1);
    reinterpret_cast<uint2*>(g_AGG16)[(size_t)warp * 32 + lane] = outv;
}

// ---------------- pooling (run-length, batch sorted) --------------------------
__global__ void k_zero_pool() {
    int i = blockIdx.x * blockDim.x + threadIdx.x;
    if (i < NG * DIM) g_sums[i] = 0.f;
    if (i < NG) g_cnt[i] = 0.f;
}
#define PCHUNK 32
__global__ __launch_bounds__(256) void k_pool(const int* __restrict__ batch,
                                              const float* __restrict__ bias, int n) {
    int warp = (blockIdx.x * blockDim.x + threadIdx.x) >> 5;
    int lane = threadIdx.x & 31;
    int q = lane * 4;
    int n0 = warp * PCHUNK;
    if (n0 >= n) return;
    int n1 = min(n0 + PCHUNK, n);

    float b0 = bias[q], b1 = bias[q + 1], b2 = bias[q + 2], b3 = bias[q + 3];
    const uint2* Av = reinterpret_cast<const uint2*>(g_AGG16);

    float4 acc = make_float4(0.f, 0.f, 0.f, 0.f);
    float cnt = 0.f;
    int cur = batch[n0];
    for (int node = n0; node < n1; node++) {
        int bb = batch[node];
        if (bb != cur) {
            float* p = &g_sums[cur * DIM + q];
            asm volatile("red.global.add.v4.f32 [%0], {%1, %2, %3, %4};"
                         :: "l"(p), "f"(acc.x), "f"(acc.y), "f"(acc.z), "f"(acc.w) : "memory");
            if (lane == 0) atomicAdd(&g_cnt[cur], cnt);
            acc = make_float4(0.f, 0.f, 0.f, 0.f);
            cnt = 0.f;
            cur = bb;
        }
        uint2 raw = Av[(size_t)node * 32 + lane];
        float2 f0 = __half22float2(*reinterpret_cast<__half2*>(&raw.x));
        float2 f1 = __half22float2(*reinterpret_cast<__half2*>(&raw.y));
        acc.x += fmaxf(f0.x + b0, 0.f);
        acc.y += fmaxf(f0.y + b1, 0.f);
        acc.z += fmaxf(f1.x + b2, 0.f);
        acc.w += fmaxf(f1.y + b3, 0.f);
        cnt += 1.f;
    }
    float* p = &g_sums[cur * DIM + q];
    asm volatile("red.global.add.v4.f32 [%0], {%1, %2, %3, %4};"
                 :: "l"(p), "f"(acc.x), "f"(acc.y), "f"(acc.z), "f"(acc.w) : "memory");
    if (lane == 0) atomicAdd(&g_cnt[cur], cnt);
}

// ---------------- head --------------------------------------------------------
__global__ void k_lin1(const float* __restrict__ w1, const float* __restrict__ b1) {
    int g = blockIdx.x;
    int j = threadIdx.x;
    __shared__ float srow[DIM];
    float inv = 1.0f / fmaxf(g_cnt[g], 1.0f);
    srow[j] = g_sums[g * DIM + j] * inv;
    __syncthreads();
    float acc = b1[j];
#pragma unroll 8
    for (int k = 0; k < DIM; k++) acc += srow[k] * w1[k * DIM + j];
    g_G1[g * DIM + j] = fmaxf(acc, 0.f);
}
__global__ void k_head(const float* __restrict__ w2, const float* __restrict__ b2,
                       float* __restrict__ out) {
    int g = threadIdx.x;
    if (g >= NG) return;
    float l0 = b2[0], l1 = b2[1];
#pragma unroll 8
    for (int k = 0; k < DIM; k++) {
        float v = g_G1[g * DIM + k];
        l0 += v * w2[k * 2 + 0];
        l1 += v * w2[k * 2 + 1];
    }
    float m   = fmaxf(l0, l1);
    float lse = m + logf(expf(l0 - m) + expf(l1 - m));
    out[g * 2 + 0] = l0 - lse;
    out[g * 2 + 1] = l1 - lse;
}

// ---------------- launch ------------------------------------------------------
extern "C" void kernel_launch(void* const* d_in, const int* in_sizes, int n_in,
                              void* d_out, int out_size) {
    const float* x      = (const float*)d_in[0];
    const int*   ei     = (const int*)d_in[1];
    const int*   batch  = (const int*)d_in[2];
    const float* conv_w = (const float*)d_in[3];
    const float* conv_b = (const float*)d_in[4];
    const float* lin1_w = (const float*)d_in[5];
    const float* lin1_b = (const float*)d_in[6];
    const float* lin2_w = (const float*)d_in[7];
    const float* lin2_b = (const float*)d_in[8];
    float* out = (float*)d_out;

    int N = in_sizes[2];
    int E = in_sizes[1] / 2;
    const int* src = ei;
    const int* dst = ei + E;

    k_zero_deg<<<(N + 255) / 256, 256>>>(N);
    k_deg<<<(E + 255) / 256, 256>>>(dst, E);
    k_dinv<<<(N + 255) / 256, 256>>>(N);

    int nb = (N + 511) / 512;
    k_scan1<<<nb, 512>>>(N);
    k_scan2<<<1, 256>>>(nb);
    k_scan3<<<nb, 512>>>(N, E);
    k_fill<<<(E + 255) / 256, 256>>>(src, dst, E);

    int gemm_blocks   = (N + 127) / 128;
    int gather_blocks = (N * 32 + 255) / 256;

    for (int l = 0; l < 3; l++) {
        const float* bias = (l > 0) ? (conv_b + (size_t)(l - 1) * DIM) : conv_b;
        k_gemm_mma<<<gemm_blocks, 256>>>(x, conv_w + (size_t)l * DIM * DIM, bias,
                                         l > 0 ? 1 : 0, N);
        k_gather<<<gather_blocks, 256>>>(N);
    }

    k_zero_pool<<<(NG * DIM + 255) / 256, 256>>>();
    int pool_warps = (N + PCHUNK - 1) / PCHUNK;
    k_pool<<<(pool_warps * 32 + 255) / 256, 256>>>(batch, conv_b + (size_t)2 * DIM, N);
    k_lin1<<<NG, DIM>>>(lin1_w, lin1_b);
    k_head<<<1, NG>>>(lin2_w, lin2_b, out);
}